// round 5
// baseline (speedup 1.0000x reference)
#include <cuda_runtime.h>
#include <cstdint>

// out[b,n,m] = sum_d x1[b,n,d]*x2[b,m,d] + const   (B=4, N=M=4096, D=32, fp32)
//
// Round 5: mma.sync tf32 + smem-bounce epilogue with a DEDICATED C buffer
// (dynamic smem). Fixes R4's regression: no chunking -> no idle warps, only
// one extra barrier, and C stride 136 makes STS.64 bank-conflict-free
// (8g+2t4 distinct per 16-lane phase).

#define TILE 128
#define DDIM 32
#define ROW_WORDS 34                 // staging: 32 data + 2 pad words
#define TILE_WORDS (128 * ROW_WORDS) // 4352
#define C_STRIDE 136                 // 136 mod 32 = 8 -> conflict-free STS.64
#define SMEM_WORDS (2 * TILE_WORDS + 128 * C_STRIDE)   // 8704 + 17408 = 26112
#define SMEM_BYTES (SMEM_WORDS * 4)                    // 104448 B

__device__ __forceinline__ uint32_t f32_to_tf32(float f) {
    uint32_t r;
    asm("cvt.rna.tf32.f32 %0, %1;" : "=r"(r) : "f"(f));
    return r;
}

__device__ __forceinline__ void mma_tf32_16x8x8(
    float& d0, float& d1, float& d2, float& d3,
    uint32_t a0, uint32_t a1, uint32_t a2, uint32_t a3,
    uint32_t b0, uint32_t b1) {
    asm volatile(
        "mma.sync.aligned.m16n8k8.row.col.f32.tf32.tf32.f32 "
        "{%0,%1,%2,%3}, {%4,%5,%6,%7}, {%8,%9}, {%0,%1,%2,%3};"
        : "+f"(d0), "+f"(d1), "+f"(d2), "+f"(d3)
        : "r"(a0), "r"(a1), "r"(a2), "r"(a3), "r"(b0), "r"(b1));
}

__global__ __launch_bounds__(256, 2)
void bmm_mma_kernel(const float* __restrict__ x1,
                    const float* __restrict__ x2,
                    const float* __restrict__ cptr,
                    float* __restrict__ out) {
    extern __shared__ uint32_t sbuf[];
    uint32_t* As = sbuf;
    uint32_t* Bs = sbuf + TILE_WORDS;
    float*    Cs = (float*)(sbuf + 2 * TILE_WORDS);

    const int tid = threadIdx.x;
    const int wid = tid >> 5;
    const int lid = tid & 31;
    const int g   = lid >> 2;     // groupID 0..7
    const int t4  = lid & 3;      // thread-in-group 0..3
    const int warp_m = wid & 3;   // 0..3  (32-row block)
    const int warp_n = wid >> 2;  // 0..1  (64-col block)
    const int b = blockIdx.z;
    const int N = 4096, M = 4096;

    // ---- Stage tiles: gmem fp32 -> tf32 -> permuted smem ----
    // newcol(c) = (c&3)*8 + (c>>2): float4 at cols 4q..4q+3 scatters to
    // words q, q+8, q+16, q+24 of the row.
    const float* a_base = x1 + ((size_t)b * N + (size_t)blockIdx.y * TILE) * DDIM;
    const float* b_base = x2 + ((size_t)b * M + (size_t)blockIdx.x * TILE) * DDIM;
    #pragma unroll
    for (int i = 0; i < 4; i++) {
        int s = tid + i * 256;        // 0..1023
        int row = s >> 3;             // 0..127
        int q   = s & 7;              // float4 index within row
        float4 va = *(const float4*)(a_base + (size_t)row * DDIM + q * 4);
        uint32_t* da = &As[row * ROW_WORDS + q];
        da[0]  = f32_to_tf32(va.x);
        da[8]  = f32_to_tf32(va.y);
        da[16] = f32_to_tf32(va.z);
        da[24] = f32_to_tf32(va.w);
        float4 vb = *(const float4*)(b_base + (size_t)row * DDIM + q * 4);
        uint32_t* db = &Bs[row * ROW_WORDS + q];
        db[0]  = f32_to_tf32(vb.x);
        db[8]  = f32_to_tf32(vb.y);
        db[16] = f32_to_tf32(vb.z);
        db[24] = f32_to_tf32(vb.w);
    }
    const float cbias = cptr[0];
    __syncthreads();

    // ---- MMA mainloop ----
    float acc[2][8][4];
    #pragma unroll
    for (int mt = 0; mt < 2; mt++)
        #pragma unroll
        for (int nt = 0; nt < 8; nt++)
            #pragma unroll
            for (int r = 0; r < 4; r++)
                acc[mt][nt][r] = 0.0f;

    const int frag_word = t4 * 8;   // + 2j selects the k-step pair
    #pragma unroll
    for (int j = 0; j < 4; j++) {
        uint2 apair[2][2];
        #pragma unroll
        for (int mt = 0; mt < 2; mt++) {
            int row0 = warp_m * 32 + mt * 16 + g;
            apair[mt][0] = *(const uint2*)&As[row0 * ROW_WORDS + frag_word + 2 * j];
            apair[mt][1] = *(const uint2*)&As[(row0 + 8) * ROW_WORDS + frag_word + 2 * j];
        }
        uint2 bpair[8];
        #pragma unroll
        for (int nt = 0; nt < 8; nt++) {
            int brow = warp_n * 64 + nt * 8 + g;
            bpair[nt] = *(const uint2*)&Bs[brow * ROW_WORDS + frag_word + 2 * j];
        }
        #pragma unroll
        for (int mt = 0; mt < 2; mt++)
            #pragma unroll
            for (int nt = 0; nt < 8; nt++)
                mma_tf32_16x8x8(acc[mt][nt][0], acc[mt][nt][1],
                                acc[mt][nt][2], acc[mt][nt][3],
                                apair[mt][0].x, apair[mt][1].x,
                                apair[mt][0].y, apair[mt][1].y,
                                bpair[nt].x, bpair[nt].y);
    }

    // ---- Epilogue: acc -> dedicated C smem (bias added), one sync,
    //      then cooperative full-line STG.128 ----
    // STS.64: word = 136*(row) + col; banks (8g + 2t4) mod 32 -> conflict-free.
    #pragma unroll
    for (int mt = 0; mt < 2; mt++) {
        int r0 = warp_m * 32 + mt * 16 + g;
        #pragma unroll
        for (int nt = 0; nt < 8; nt++) {
            int c0 = warp_n * 64 + nt * 8 + 2 * t4;
            *(float2*)&Cs[r0 * C_STRIDE + c0] =
                make_float2(acc[mt][nt][0] + cbias, acc[mt][nt][1] + cbias);
            *(float2*)&Cs[(r0 + 8) * C_STRIDE + c0] =
                make_float2(acc[mt][nt][2] + cbias, acc[mt][nt][3] + cbias);
        }
    }
    __syncthreads();

    const size_t grow0 = (size_t)b * N + (size_t)blockIdx.y * TILE;
    const size_t gcol  = (size_t)blockIdx.x * TILE + lid * 4;
    #pragma unroll
    for (int i = 0; i < 16; i++) {
        int r = i * 8 + wid;
        float4 v = *(const float4*)&Cs[r * C_STRIDE + lid * 4];
        *(float4*)(out + (grow0 + r) * M + gcol) = v;
    }
}

extern "C" void kernel_launch(void* const* d_in, const int* in_sizes, int n_in,
                              void* d_out, int out_size) {
    const float* x1  = (const float*)d_in[0];   // [4, 4096, 32]
    const float* x2  = (const float*)d_in[1];   // [4, 4096, 32]
    const float* cst = (const float*)d_in[2];   // [1]
    float* out       = (float*)d_out;           // [4, 4096, 4096]

    static bool attr_done = false;
    if (!attr_done) {
        cudaFuncSetAttribute(bmm_mma_kernel,
                             cudaFuncAttributeMaxDynamicSharedMemorySize,
                             SMEM_BYTES);
        attr_done = true;
    }

    dim3 grid(4096 / TILE, 4096 / TILE, 4);
    bmm_mma_kernel<<<grid, 256, SMEM_BYTES>>>(x1, x2, cst, out);
}

// round 6
// speedup vs baseline: 1.1025x; 1.1025x over previous
#include <cuda_runtime.h>
#include <cstdint>

// out[b,n,m] = sum_d x1[b,n,d]*x2[b,m,d] + const   (B=4, N=M=4096, D=32, fp32)
//
// Round 6: mma.sync tf32, tile 128x64, 4 CTAs/SM (occupancy fix), and an
// output-column PERMUTATION of the B smem rows so each thread's epilogue
// fragment covers 8 contiguous gmem columns -> pure STG.128, no smem bounce,
// no extra barriers. Warp tile 32x32 (4m x 2n warps), acc = 32 regs.

#define TILE_M 128
#define TILE_N 64
#define DDIM 32
#define ROW_WORDS 34                         // 32 data + 2 pad words
#define A_WORDS (TILE_M * ROW_WORDS)         // 4352
#define B_WORDS (TILE_N * ROW_WORDS)         // 2176

__device__ __forceinline__ uint32_t f32_to_tf32(float f) {
    uint32_t r;
    asm("cvt.rna.tf32.f32 %0, %1;" : "=r"(r) : "f"(f));
    return r;
}

__device__ __forceinline__ void mma_tf32_16x8x8(
    float& d0, float& d1, float& d2, float& d3,
    uint32_t a0, uint32_t a1, uint32_t a2, uint32_t a3,
    uint32_t b0, uint32_t b1) {
    asm volatile(
        "mma.sync.aligned.m16n8k8.row.col.f32.tf32.tf32.f32 "
        "{%0,%1,%2,%3}, {%4,%5,%6,%7}, {%8,%9}, {%0,%1,%2,%3};"
        : "+f"(d0), "+f"(d1), "+f"(d2), "+f"(d3)
        : "r"(a0), "r"(a1), "r"(a2), "r"(a3), "r"(b0), "r"(b1));
}

// Output-column permutation: smem B slot for x2 tile-row r.
// Within each 32-block: r = 8b + 2a + e  ->  slot u = 8a + 2b + e.
// Then mma c-frag col (8*nt + 2*t4 + e) corresponds to gmem col
// (8*t4 + 2*nt + e): thread fragments are gmem-contiguous.
__device__ __forceinline__ int bperm(int r) {
    int blk = r & ~31;
    int u = r & 31;
    int a = u >> 3, b = (u & 7) >> 1, e = u & 1;
    return blk + (b << 3) + (a << 1) + e;
}

__global__ __launch_bounds__(256, 4)
void bmm_mma_kernel(const float* __restrict__ x1,
                    const float* __restrict__ x2,
                    const float* __restrict__ cptr,
                    float* __restrict__ out) {
    __shared__ uint32_t As[A_WORDS];
    __shared__ uint32_t Bs[B_WORDS];

    const int tid = threadIdx.x;
    const int wid = tid >> 5;
    const int lid = tid & 31;
    const int g   = lid >> 2;     // groupID 0..7
    const int t4  = lid & 3;      // thread-in-group 0..3
    const int warp_m = wid & 3;   // 0..3  (32-row block)
    const int warp_n = wid >> 2;  // 0..1  (32-col block)
    const int b = blockIdx.z;
    const int N = 4096, M = 4096;

    // ---- Stage A: 128 rows. k-permuted cols: float4 q -> words q,q+8,q+16,q+24.
    const float* a_base = x1 + ((size_t)b * N + (size_t)blockIdx.y * TILE_M) * DDIM;
    #pragma unroll
    for (int i = 0; i < 4; i++) {
        int s = tid + i * 256;        // 0..1023
        int row = s >> 3;
        int q   = s & 7;
        float4 va = *(const float4*)(a_base + (size_t)row * DDIM + q * 4);
        uint32_t* da = &As[row * ROW_WORDS + q];
        da[0]  = f32_to_tf32(va.x);
        da[8]  = f32_to_tf32(va.y);
        da[16] = f32_to_tf32(va.z);
        da[24] = f32_to_tf32(va.w);
    }
    // ---- Stage B: 64 rows into PERMUTED slots.
    const float* b_base = x2 + ((size_t)b * M + (size_t)blockIdx.x * TILE_N) * DDIM;
    #pragma unroll
    for (int i = 0; i < 2; i++) {
        int s = tid + i * 256;        // 0..511
        int row = s >> 3;
        int q   = s & 7;
        float4 vb = *(const float4*)(b_base + (size_t)row * DDIM + q * 4);
        uint32_t* db = &Bs[bperm(row) * ROW_WORDS + q];
        db[0]  = f32_to_tf32(vb.x);
        db[8]  = f32_to_tf32(vb.y);
        db[16] = f32_to_tf32(vb.z);
        db[24] = f32_to_tf32(vb.w);
    }
    const float cbias = cptr[0];
    __syncthreads();

    // ---- MMA mainloop: warp tile 32x32, 4 k-steps of 8 ----
    float acc[2][4][4];
    #pragma unroll
    for (int mt = 0; mt < 2; mt++)
        #pragma unroll
        for (int nt = 0; nt < 4; nt++)
            #pragma unroll
            for (int r = 0; r < 4; r++)
                acc[mt][nt][r] = 0.0f;

    const int frag_word = t4 * 8;   // + 2j selects the k-step pair
    #pragma unroll
    for (int j = 0; j < 4; j++) {
        uint2 apair[2][2];
        #pragma unroll
        for (int mt = 0; mt < 2; mt++) {
            int row0 = warp_m * 32 + mt * 16 + g;
            apair[mt][0] = *(const uint2*)&As[row0 * ROW_WORDS + frag_word + 2 * j];
            apair[mt][1] = *(const uint2*)&As[(row0 + 8) * ROW_WORDS + frag_word + 2 * j];
        }
        uint2 bpair[4];
        #pragma unroll
        for (int nt = 0; nt < 4; nt++) {
            int brow = warp_n * 32 + nt * 8 + g;
            bpair[nt] = *(const uint2*)&Bs[brow * ROW_WORDS + frag_word + 2 * j];
        }
        #pragma unroll
        for (int mt = 0; mt < 2; mt++)
            #pragma unroll
            for (int nt = 0; nt < 4; nt++)
                mma_tf32_16x8x8(acc[mt][nt][0], acc[mt][nt][1],
                                acc[mt][nt][2], acc[mt][nt][3],
                                apair[mt][0].x, apair[mt][1].x,
                                apair[mt][0].y, apair[mt][1].y,
                                bpair[nt].x, bpair[nt].y);
    }

    // ---- Epilogue: permutation makes each thread's 8 values per row
    //      contiguous gmem columns -> two STG.128 per row, no bounce. ----
    // c-frag col 8nt+2t4+e  ==  gmem col 8t4+2nt+e (within warp 32-block).
    const size_t row_base = (size_t)b * N + (size_t)blockIdx.y * TILE_M + warp_m * 32;
    const size_t col0 = (size_t)blockIdx.x * TILE_N + warp_n * 32 + 8 * t4;
    #pragma unroll
    for (int mt = 0; mt < 2; mt++) {
        size_t r0 = row_base + mt * 16 + g;
        float* p0 = out + r0 * M + col0;         // row g
        float* p1 = out + (r0 + 8) * M + col0;   // row g+8
        float4 v;
        v = make_float4(acc[mt][0][0] + cbias, acc[mt][0][1] + cbias,
                        acc[mt][1][0] + cbias, acc[mt][1][1] + cbias);
        *(float4*)(p0) = v;
        v = make_float4(acc[mt][2][0] + cbias, acc[mt][2][1] + cbias,
                        acc[mt][3][0] + cbias, acc[mt][3][1] + cbias);
        *(float4*)(p0 + 4) = v;
        v = make_float4(acc[mt][0][2] + cbias, acc[mt][0][3] + cbias,
                        acc[mt][1][2] + cbias, acc[mt][1][3] + cbias);
        *(float4*)(p1) = v;
        v = make_float4(acc[mt][2][2] + cbias, acc[mt][2][3] + cbias,
                        acc[mt][3][2] + cbias, acc[mt][3][3] + cbias);
        *(float4*)(p1 + 4) = v;
    }
}

extern "C" void kernel_launch(void* const* d_in, const int* in_sizes, int n_in,
                              void* d_out, int out_size) {
    const float* x1  = (const float*)d_in[0];   // [4, 4096, 32]
    const float* x2  = (const float*)d_in[1];   // [4, 4096, 32]
    const float* cst = (const float*)d_in[2];   // [1]
    float* out       = (float*)d_out;           // [4, 4096, 4096]

    dim3 grid(4096 / TILE_N, 4096 / TILE_M, 4);
    bmm_mma_kernel<<<grid, 256>>>(x1, x2, cst, out);
}

// round 7
// speedup vs baseline: 1.2217x; 1.1081x over previous
#include <cuda_runtime.h>
#include <cstdint>

// out[b,n,m] = sum_d x1[b,n,d]*x2[b,m,d] + const   (B=4, N=M=4096, D=32, fp32)
//
// Round 7: R6 pipeline with minimal-wavefront smem staging.
//  - Identity k-column layout + 16B-granular XOR swizzle (q' = q ^ 2*(row&3)),
//    stride 32 words (ZERO padding): staging is one conflict-free STS.128 per
//    float4 (wf floor), mainloop LDS.64 stays conflict-free
//    (banks = 8*(j^g) + 2*t4, disjoint fields).
//  - k-relabeling is legal: mma's sum_k a_k*b_k is invariant when A and B use
//    the same k-slot assignment (thread t4 supplies k=2t4,2t4+1 of each 8-blk).
//  - B row-permutation (bperm) kept: epilogue stays contiguous STG.128.

#define TILE_M 128
#define TILE_N 64
#define DDIM 32
#define A_WORDS (TILE_M * 32)       // 4096 words, 16KB
#define B_WORDS (TILE_N * 32)       // 2048 words, 8KB

__device__ __forceinline__ uint32_t f32_to_tf32(float f) {
    uint32_t r;
    asm("cvt.rna.tf32.f32 %0, %1;" : "=r"(r) : "f"(f));
    return r;
}

__device__ __forceinline__ void mma_tf32_16x8x8(
    float& d0, float& d1, float& d2, float& d3,
    uint32_t a0, uint32_t a1, uint32_t a2, uint32_t a3,
    uint32_t b0, uint32_t b1) {
    asm volatile(
        "mma.sync.aligned.m16n8k8.row.col.f32.tf32.tf32.f32 "
        "{%0,%1,%2,%3}, {%4,%5,%6,%7}, {%8,%9}, {%0,%1,%2,%3};"
        : "+f"(d0), "+f"(d1), "+f"(d2), "+f"(d3)
        : "r"(a0), "r"(a1), "r"(a2), "r"(a3), "r"(b0), "r"(b1));
}

// B row permutation (involution): within each 32-block, r = 8b+2a+e -> 8a+2b+e.
// Makes mma frag col (8nt+2t4+e) correspond to gmem col (8t4+2nt+e):
// each thread's 8 values per output row are contiguous -> STG.128 epilogue.
__device__ __forceinline__ int bperm(int r) {
    int blk = r & ~31;
    int u = r & 31;
    int a = u >> 3, bb = (u & 7) >> 1, e = u & 1;
    return blk + (bb << 3) + (a << 1) + e;
}

__global__ __launch_bounds__(256, 4)
void bmm_mma_kernel(const float* __restrict__ x1,
                    const float* __restrict__ x2,
                    const float* __restrict__ cptr,
                    float* __restrict__ out) {
    __shared__ uint32_t As[A_WORDS];
    __shared__ uint32_t Bs[B_WORDS];

    const int tid = threadIdx.x;
    const int wid = tid >> 5;
    const int lid = tid & 31;
    const int g   = lid >> 2;     // groupID 0..7
    const int t4  = lid & 3;      // thread-in-group 0..3
    const int warp_m = wid & 3;   // 0..3  (32-row block)
    const int warp_n = wid >> 2;  // 0..1  (32-col block)
    const int b = blockIdx.z;
    const int N = 4096, M = 4096;

    // ---- Stage A: one conflict-free STS.128 per float4 ----
    const float* a_base = x1 + ((size_t)b * N + (size_t)blockIdx.y * TILE_M) * DDIM;
    #pragma unroll
    for (int i = 0; i < 4; i++) {
        int s = tid + i * 256;        // 0..1023
        int row = s >> 3;
        int q   = s & 7;
        float4 va = *(const float4*)(a_base + (size_t)row * DDIM + q * 4);
        uint4 t = make_uint4(f32_to_tf32(va.x), f32_to_tf32(va.y),
                             f32_to_tf32(va.z), f32_to_tf32(va.w));
        int qp = q ^ (2 * (row & 3));          // 16B-unit XOR swizzle
        *(uint4*)&As[row * 32 + 4 * qp] = t;
    }
    // ---- Stage B: permuted row slot, same swizzle (keyed on SLOT) ----
    const float* b_base = x2 + ((size_t)b * M + (size_t)blockIdx.x * TILE_N) * DDIM;
    #pragma unroll
    for (int i = 0; i < 2; i++) {
        int s = tid + i * 256;        // 0..511
        int row = s >> 3;
        int q   = s & 7;
        float4 vb = *(const float4*)(b_base + (size_t)row * DDIM + q * 4);
        uint4 t = make_uint4(f32_to_tf32(vb.x), f32_to_tf32(vb.y),
                             f32_to_tf32(vb.z), f32_to_tf32(vb.w));
        int slot = bperm(row);
        int qp = q ^ (2 * (slot & 3));
        *(uint4*)&Bs[slot * 32 + 4 * qp] = t;
    }
    const float cbias = cptr[0];
    __syncthreads();

    // ---- MMA mainloop: warp tile 32x32, 4 k-steps of 8 ----
    float acc[2][4][4];
    #pragma unroll
    for (int mt = 0; mt < 2; mt++)
        #pragma unroll
        for (int nt = 0; nt < 4; nt++)
            #pragma unroll
            for (int r = 0; r < 4; r++)
                acc[mt][nt][r] = 0.0f;

    const int gx = g & 3;
    const int arow0 = warp_m * 32 + g;          // mt adds 16, second row +8
    const int brow0 = warp_n * 32 + g;          // nt adds 8
    #pragma unroll
    for (int j = 0; j < 4; j++) {
        // swizzled column offset for this thread's k-pair in k-block j
        const int coff = 8 * (j ^ gx) + 2 * t4;
        uint2 apair[2][2];
        #pragma unroll
        for (int mt = 0; mt < 2; mt++) {
            int r0 = arow0 + mt * 16;
            apair[mt][0] = *(const uint2*)&As[r0 * 32 + coff];
            apair[mt][1] = *(const uint2*)&As[(r0 + 8) * 32 + coff];
        }
        uint2 bpair[4];
        #pragma unroll
        for (int nt = 0; nt < 4; nt++)
            bpair[nt] = *(const uint2*)&Bs[(brow0 + nt * 8) * 32 + coff];

        #pragma unroll
        for (int mt = 0; mt < 2; mt++)
            #pragma unroll
            for (int nt = 0; nt < 4; nt++)
                mma_tf32_16x8x8(acc[mt][nt][0], acc[mt][nt][1],
                                acc[mt][nt][2], acc[mt][nt][3],
                                apair[mt][0].x, apair[mt][1].x,
                                apair[mt][0].y, apair[mt][1].y,
                                bpair[nt].x, bpair[nt].y);
    }

    // ---- Epilogue: bperm makes each thread's 8 values per row contiguous ----
    const size_t row_base = (size_t)b * N + (size_t)blockIdx.y * TILE_M + warp_m * 32;
    const size_t col0 = (size_t)blockIdx.x * TILE_N + warp_n * 32 + 8 * t4;
    #pragma unroll
    for (int mt = 0; mt < 2; mt++) {
        size_t r0 = row_base + mt * 16 + g;
        float* p0 = out + r0 * M + col0;         // row g
        float* p1 = out + (r0 + 8) * M + col0;   // row g+8
        float4 v;
        v = make_float4(acc[mt][0][0] + cbias, acc[mt][0][1] + cbias,
                        acc[mt][1][0] + cbias, acc[mt][1][1] + cbias);
        *(float4*)(p0) = v;
        v = make_float4(acc[mt][2][0] + cbias, acc[mt][2][1] + cbias,
                        acc[mt][3][0] + cbias, acc[mt][3][1] + cbias);
        *(float4*)(p0 + 4) = v;
        v = make_float4(acc[mt][0][2] + cbias, acc[mt][0][3] + cbias,
                        acc[mt][1][2] + cbias, acc[mt][1][3] + cbias);
        *(float4*)(p1) = v;
        v = make_float4(acc[mt][2][2] + cbias, acc[mt][2][3] + cbias,
                        acc[mt][3][2] + cbias, acc[mt][3][3] + cbias);
        *(float4*)(p1 + 4) = v;
    }
}

extern "C" void kernel_launch(void* const* d_in, const int* in_sizes, int n_in,
                              void* d_out, int out_size) {
    const float* x1  = (const float*)d_in[0];   // [4, 4096, 32]
    const float* x2  = (const float*)d_in[1];   // [4, 4096, 32]
    const float* cst = (const float*)d_in[2];   // [1]
    float* out       = (float*)d_out;           // [4, 4096, 4096]

    dim3 grid(4096 / TILE_N, 4096 / TILE_M, 4);
    bmm_mma_kernel<<<grid, 256>>>(x1, x2, cst, out);
}